// round 3
// baseline (speedup 1.0000x reference)
#include <cuda_runtime.h>
#include <cuda_bf16.h>
#include <math.h>
#include <stdint.h>

// ---------------- problem constants ----------------
#define LSEQ   1024
#define BATCH  8
#define CDIM   256
#define DINNER 512
#define DSTATE 16
#define NROWS  (BATCH*LSEQ)   // 8192

typedef __nv_bfloat16 bf16;
typedef __nv_bfloat162 bf162;

// ---------------- scratch (static, no allocs) ----------------
__device__ bf16   g_xnh  [(size_t)NROWS*CDIM];     // layernormed x, bf16
__device__ bf16   g_uh   [(size_t)NROWS*DINNER];   // raw u (pre-conv), bf16
__device__ float  g_gz   [(size_t)NROWS*DINNER];   // silu(z)
__device__ bf16   g_u2h  [(size_t)NROWS*DINNER];   // post conv+silu, bf16
__device__ float2 g_du   [(size_t)NROWS*DINNER];   // (dt, u2) packed
__device__ float2 g_bc   [(size_t)NROWS*DSTATE];   // (B_s, C_s) packed
__device__ bf16   g_ygh  [(size_t)NROWS*DINNER];   // y * silu(z), bf16
__device__ float  g_o    [(size_t)NROWS*CDIM];
// weights, bf16, transposed to [N][K] (K-major)
__device__ bf16   g_WinT  [(size_t)1024*CDIM];
__device__ bf16   g_wcombT[(size_t)DINNER*DINNER];
__device__ bf16   g_WbcT  [(size_t)32*DINNER];
__device__ bf16   g_WoutT [(size_t)CDIM*DINNER];

// ---------------- helpers ----------------
__device__ __forceinline__ float siluf(float v) { return v / (1.f + __expf(-v)); }
__device__ __forceinline__ float softplusf(float v) {
    return (v > 20.f) ? v : log1pf(__expf(v));
}
__device__ __forceinline__ void cp16(void* sm, const void* gm) {
    uint32_t a = (uint32_t)__cvta_generic_to_shared(sm);
    asm volatile("cp.async.cg.shared.global [%0], [%1], 16;\n" :: "r"(a), "l"(gm));
}
__device__ __forceinline__ void mma16(float* c, const uint32_t* a, const uint32_t* b) {
    asm volatile(
        "mma.sync.aligned.m16n8k16.row.col.f32.bf16.bf16.f32 "
        "{%0,%1,%2,%3}, {%4,%5,%6,%7}, {%8,%9}, {%0,%1,%2,%3};\n"
        : "+f"(c[0]), "+f"(c[1]), "+f"(c[2]), "+f"(c[3])
        : "r"(a[0]), "r"(a[1]), "r"(a[2]), "r"(a[3]), "r"(b[0]), "r"(b[1]));
}

// ---------------- LayerNorm + (B,C,H,W) -> (B,L,C) bf16 ----------------
__global__ __launch_bounds__(256) void ln_kernel(const float* __restrict__ x,
                                                 const float* __restrict__ gamma,
                                                 const float* __restrict__ beta) {
    __shared__ float sm[32*257];
    __shared__ float s_mu[32], s_rs[32];
    const int b  = blockIdx.x >> 5;
    const int l0 = (blockIdx.x & 31) * 32;
    const int t  = threadIdx.x;
    #pragma unroll
    for (int j = 0; j < 32; j++) {
        int e  = j*256 + t;
        int c  = e >> 5;
        int li = e & 31;
        sm[li*257 + c] = x[((size_t)(b*CDIM + c))*LSEQ + l0 + li];
    }
    __syncthreads();
    const int w = t >> 5, lane = t & 31;
    #pragma unroll
    for (int q = 0; q < 4; q++) {
        int li = w*4 + q;
        float s = 0.f, s2 = 0.f;
        #pragma unroll
        for (int j = 0; j < 8; j++) {
            float v = sm[li*257 + lane + j*32];
            s += v; s2 = fmaf(v, v, s2);
        }
        #pragma unroll
        for (int o = 16; o; o >>= 1) {
            s  += __shfl_xor_sync(0xffffffffu, s,  o);
            s2 += __shfl_xor_sync(0xffffffffu, s2, o);
        }
        if (lane == 0) {
            float mu  = s * (1.f/CDIM);
            float var = s2 * (1.f/CDIM) - mu*mu;
            s_mu[li] = mu;
            s_rs[li] = rsqrtf(var + 1e-5f);
        }
    }
    __syncthreads();
    const float g = gamma[t], be = beta[t];
    #pragma unroll
    for (int li = 0; li < 32; li++) {
        float v = (sm[li*257 + t] - s_mu[li]) * s_rs[li];
        g_xnh[((size_t)(b*LSEQ + l0 + li))*CDIM + t] = __float2bfloat16(fmaf(v, g, be));
    }
}

// ---------------- transpose+convert weight: dst[n][k] = src[k*ldsrc+off+n] ----------------
__global__ __launch_bounds__(256) void tconv_kernel(const float* __restrict__ src,
                                                    bf16* __restrict__ dst,
                                                    int K, int ldsrc, int coloff) {
    __shared__ float sm[32][33];
    const int n0 = blockIdx.x * 32;
    const int k0 = blockIdx.y * 32;
    const int t  = threadIdx.x;
    #pragma unroll
    for (int p = 0; p < 4; p++) {
        int ki = p*8 + (t >> 5);
        sm[ki][t & 31] = src[(size_t)(k0+ki)*ldsrc + coloff + n0 + (t & 31)];
    }
    __syncthreads();
    #pragma unroll
    for (int p = 0; p < 4; p++) {
        int ni = p*8 + (t >> 5);
        dst[(size_t)(n0+ni)*K + k0 + (t & 31)] = __float2bfloat16(sm[t & 31][ni]);
    }
}

// ---------------- wcombT[n][k] = sum_t Wx[k*48+t]*Wdt[t*512+n], bf16 ----------------
__global__ __launch_bounds__(256) void wcombT_kernel(const float* __restrict__ Wx,
                                                     const float* __restrict__ Wdt) {
    __shared__ float wd[16];
    const int n = blockIdx.x;
    if (threadIdx.x < 16) wd[threadIdx.x] = Wdt[threadIdx.x*DINNER + n];
    __syncthreads();
    for (int k = threadIdx.x; k < DINNER; k += 256) {
        float a = 0.f;
        #pragma unroll
        for (int t = 0; t < 16; t++) a = fmaf(wd[t], Wx[k*48 + t], a);
        g_wcombT[(size_t)n*DINNER + k] = __float2bfloat16(a);
    }
}

// ---------------- bf16 tensor-core GEMM, cp.async 3-stage, fused epilogues ----------------
// A[M][K] bf16 row-major, Bt[N][K] bf16 (K-major). 256 threads.
// MODE 0: Cf[M,N] fp32 (ldc)
// MODE 1: split u/z: col<512 -> Cb (bf16 u), else silu -> Caux (fp32 gz)
// MODE 2: dt pack: softplus(v + e0[col]) paired with e1 (bf16 u2) -> float4 into Cf=g_du
// MODE 3: bc pack: cols 0..15=B, 16..31=C interleave -> Cf=g_bc (BN=32, WN=32)
template<int BM, int BN, int WM, int WN, int MODE>
__global__ __launch_bounds__(256) void gemm_bf16(
    const bf16* __restrict__ A, const bf16* __restrict__ Bt,
    float* __restrict__ Cf, bf16* __restrict__ Cb, float* __restrict__ Caux,
    const float* __restrict__ e0, const bf16* __restrict__ e1,
    int K, int ldc)
{
    constexpr int BK = 32;
    constexpr int STAGES = 3;
    constexpr int LDA = BK + 8;                 // 40 bf16 = 80B rows, conflict-free frags
    __shared__ bf16 As[STAGES][BM * LDA];
    __shared__ bf16 Bs[STAGES][BN * LDA];
    const int tid  = threadIdx.x;
    const int wid  = tid >> 5, lane = tid & 31;
    const int g    = lane >> 2, q = lane & 3;
    constexpr int NWN = BN / WN;
    const int wm = wid / NWN, wn = wid % NWN;
    const int m0 = blockIdx.y * BM, n0 = blockIdx.x * BN;
    constexpr int MF = WM / 16, NF = WN / 8;
    float acc[MF][NF][4] = {};

    auto load_stage = [&](int s, int kt) {
        int k0 = kt * BK;
        #pragma unroll
        for (int i = 0; i < BM*4/256; i++) {
            int ch = tid + i*256;
            int r = ch >> 2, ko = (ch & 3)*8;
            cp16(&As[s][r*LDA + ko], &A[(size_t)(m0+r)*K + k0 + ko]);
        }
        #pragma unroll
        for (int i = 0; i < (BN*4 + 255)/256; i++) {
            int ch = tid + i*256;
            if ((BN*4 % 256 == 0) || ch < BN*4) {
                int r = ch >> 2, ko = (ch & 3)*8;
                cp16(&Bs[s][r*LDA + ko], &Bt[(size_t)(n0+r)*K + k0 + ko]);
            }
        }
        asm volatile("cp.async.commit_group;\n");
    };
    auto compute = [&](int s) {
        const uint32_t* A32 = (const uint32_t*)As[s];
        const uint32_t* B32 = (const uint32_t*)Bs[s];
        #pragma unroll
        for (int h = 0; h < 2; h++) {           // ko = h*16, pair base h*8
            uint32_t af[MF][4], bfr[NF][2];
            #pragma unroll
            for (int i = 0; i < MF; i++) {
                int r = wm*WM + i*16 + g;
                af[i][0] = A32[(r  )*(LDA/2) + h*8 + q];
                af[i][1] = A32[(r+8)*(LDA/2) + h*8 + q];
                af[i][2] = A32[(r  )*(LDA/2) + h*8 + q + 4];
                af[i][3] = A32[(r+8)*(LDA/2) + h*8 + q + 4];
            }
            #pragma unroll
            for (int j = 0; j < NF; j++) {
                int c = wn*WN + j*8 + g;
                bfr[j][0] = B32[c*(LDA/2) + h*8 + q];
                bfr[j][1] = B32[c*(LDA/2) + h*8 + q + 4];
            }
            #pragma unroll
            for (int i = 0; i < MF; i++)
                #pragma unroll
                for (int j = 0; j < NF; j++)
                    mma16(acc[i][j], af[i], bfr[j]);
        }
    };

    const int nk = K / BK;
    #pragma unroll
    for (int s = 0; s < STAGES-1; s++) load_stage(s, s);
    #pragma unroll 1
    for (int kt = 0; kt < nk; kt++) {
        asm volatile("cp.async.wait_group %0;\n" :: "n"(STAGES-2));
        __syncthreads();
        int f = kt + STAGES - 1;
        if (f < nk) load_stage(f % STAGES, f);
        else asm volatile("cp.async.commit_group;\n");
        compute(kt % STAGES);
    }

    // ----- epilogue -----
    #pragma unroll
    for (int i = 0; i < MF; i++) {
        int row = m0 + wm*WM + i*16 + g;
        if (MODE == 3) {
            #pragma unroll
            for (int j = 0; j < 2; j++) {
                int s = j*8 + 2*q;
                float4 lo = make_float4(acc[i][j][0], acc[i][j+2][0],
                                        acc[i][j][1], acc[i][j+2][1]);
                float4 hi = make_float4(acc[i][j][2], acc[i][j+2][2],
                                        acc[i][j][3], acc[i][j+2][3]);
                *(float4*)&Cf[((size_t)(row  )*DSTATE + s)*2] = lo;
                *(float4*)&Cf[((size_t)(row+8)*DSTATE + s)*2] = hi;
            }
        } else {
            #pragma unroll
            for (int j = 0; j < NF; j++) {
                int col = n0 + wn*WN + j*8 + 2*q;
                float v0 = acc[i][j][0], v1 = acc[i][j][1];
                float v2 = acc[i][j][2], v3 = acc[i][j][3];
                if (MODE == 0) {
                    *(float2*)&Cf[(size_t)(row  )*ldc + col] = make_float2(v0, v1);
                    *(float2*)&Cf[(size_t)(row+8)*ldc + col] = make_float2(v2, v3);
                } else if (MODE == 1) {
                    if (col < DINNER) {
                        *(bf162*)&Cb[(size_t)(row  )*DINNER + col] =
                            __floats2bfloat162_rn(v0, v1);
                        *(bf162*)&Cb[(size_t)(row+8)*DINNER + col] =
                            __floats2bfloat162_rn(v2, v3);
                    } else {
                        int cz = col - DINNER;
                        *(float2*)&Caux[(size_t)(row  )*DINNER + cz] =
                            make_float2(siluf(v0), siluf(v1));
                        *(float2*)&Caux[(size_t)(row+8)*DINNER + cz] =
                            make_float2(siluf(v2), siluf(v3));
                    }
                } else { // MODE 2
                    float bd0 = e0[col], bd1 = e0[col+1];
                    bf162 ua = *(const bf162*)&e1[(size_t)(row  )*DINNER + col];
                    bf162 ub = *(const bf162*)&e1[(size_t)(row+8)*DINNER + col];
                    float4 oa = make_float4(softplusf(v0 + bd0), __bfloat162float(ua.x),
                                            softplusf(v1 + bd1), __bfloat162float(ua.y));
                    float4 ob = make_float4(softplusf(v2 + bd0), __bfloat162float(ub.x),
                                            softplusf(v3 + bd1), __bfloat162float(ub.y));
                    *(float4*)&Cf[((size_t)(row  )*DINNER + col)*2] = oa;
                    *(float4*)&Cf[((size_t)(row+8)*DINNER + col)*2] = ob;
                }
            }
        }
    }
}

// ---------------- depthwise causal conv (D_CONV=4) + SiLU, bf16 io ----------------
__global__ __launch_bounds__(256) void conv_silu_kernel(const float* __restrict__ cw,
                                                        const float* __restrict__ cb) {
    int gid = blockIdx.x*256 + threadIdx.x;   // over NROWS*DINNER
    int d   = gid & (DINNER-1);
    int row = gid >> 9;
    int l   = row & (LSEQ-1);
    float acc = cb[d];
    #pragma unroll
    for (int k = 0; k < 4; k++) {
        int ll = l - 3 + k;
        if (ll >= 0)
            acc = fmaf(__bfloat162float(g_uh[((size_t)(row - 3 + k))*DINNER + d]),
                       cw[d*4+k], acc);
    }
    g_u2h[gid] = __float2bfloat16(siluf(acc));
}

// ---------------- selective scan: warp = 2 channels, lane-per-state ----------------
__global__ __launch_bounds__(256) void scan_kernel(const float* __restrict__ A_log,
                                                   const float* __restrict__ D_skip) {
    int gw   = (blockIdx.x * 256 + threadIdx.x) >> 5;   // 0..2047
    int lane = threadIdx.x & 31;
    int b    = gw >> 8;
    int pair = gw & 255;
    int d    = pair*2 + (lane >> 4);
    int s    = lane & 15;
    float Aval = -__expf(A_log[d*DSTATE + s]);
    float Dd   = D_skip[d];
    size_t rb = (size_t)b * LSEQ;
    const float2* duP = g_du + rb*DINNER + d;
    const float2* bcP = g_bc + rb*DSTATE + s;
    const float*  gzP = g_gz + rb*DINNER + d;
    bf16*         ygP = g_ygh + rb*DINNER + d;
    float h = 0.f;
    for (int l = 0; l < LSEQ; l++) {
        float2 du  = duP[(size_t)l*DINNER];
        float2 bcv = bcP[(size_t)l*DSTATE];
        float dA = __expf(du.x * Aval);
        h = fmaf(dA, h, du.x * du.y * bcv.x);
        float p = h * bcv.y;
        p += __shfl_xor_sync(0xffffffffu, p, 8);
        p += __shfl_xor_sync(0xffffffffu, p, 4);
        p += __shfl_xor_sync(0xffffffffu, p, 2);
        p += __shfl_xor_sync(0xffffffffu, p, 1);
        if (s == 0) {
            float yv = p + du.y * Dd;
            ygP[(size_t)l*DINNER] = __float2bfloat16(yv * gzP[(size_t)l*DINNER]);
        }
    }
}

// ---------------- o(B,L,C) -> out(B,C,H,W) + residual x ----------------
__global__ __launch_bounds__(256) void out_kernel(const float* __restrict__ x,
                                                  float* __restrict__ out) {
    __shared__ float sm[32][33];
    const int b  = blockIdx.z;
    const int c0 = blockIdx.y * 32;
    const int l0 = blockIdx.x * 32;
    const int t  = threadIdx.x;
    const int ci = t & 31, lq = t >> 5;
    #pragma unroll
    for (int p = 0; p < 4; p++) {
        int li = p*8 + lq;
        sm[li][ci] = g_o[((size_t)(b*LSEQ + l0 + li))*CDIM + c0 + ci];
    }
    __syncthreads();
    const int li2 = t & 31, cq = t >> 5;
    #pragma unroll
    for (int p = 0; p < 4; p++) {
        int ci2 = p*8 + cq;
        size_t idx = ((size_t)(b*CDIM + c0 + ci2))*LSEQ + l0 + li2;
        out[idx] = sm[li2][ci2] + x[idx];
    }
}

// ---------------- host launch ----------------
extern "C" void kernel_launch(void* const* d_in, const int* in_sizes, int n_in,
                              void* d_out, int out_size) {
    const float* x       = (const float*)d_in[0];
    const float* ln_g    = (const float*)d_in[1];
    const float* ln_b    = (const float*)d_in[2];
    const float* W_in    = (const float*)d_in[3];
    const float* conv_w  = (const float*)d_in[4];
    const float* conv_b  = (const float*)d_in[5];
    const float* W_xproj = (const float*)d_in[6];
    const float* W_dt    = (const float*)d_in[7];
    const float* b_dt    = (const float*)d_in[8];
    const float* A_log   = (const float*)d_in[9];
    const float* D_skip  = (const float*)d_in[10];
    const float* W_out   = (const float*)d_in[11];
    float* out = (float*)d_out;

    bf16 *p_xnh, *p_uh, *p_u2h, *p_ygh, *p_WinT, *p_wcombT, *p_WbcT, *p_WoutT;
    float *p_gz, *p_o;
    float2 *p_du, *p_bc;
    cudaGetSymbolAddress((void**)&p_xnh,    g_xnh);
    cudaGetSymbolAddress((void**)&p_uh,     g_uh);
    cudaGetSymbolAddress((void**)&p_gz,     g_gz);
    cudaGetSymbolAddress((void**)&p_u2h,    g_u2h);
    cudaGetSymbolAddress((void**)&p_du,     g_du);
    cudaGetSymbolAddress((void**)&p_bc,     g_bc);
    cudaGetSymbolAddress((void**)&p_ygh,    g_ygh);
    cudaGetSymbolAddress((void**)&p_o,      g_o);
    cudaGetSymbolAddress((void**)&p_WinT,   g_WinT);
    cudaGetSymbolAddress((void**)&p_wcombT, g_wcombT);
    cudaGetSymbolAddress((void**)&p_WbcT,   g_WbcT);
    cudaGetSymbolAddress((void**)&p_WoutT,  g_WoutT);

    // 0. weight conversion / transposition (bf16, K-major)
    tconv_kernel<<<dim3(1024/32, 256/32), 256>>>(W_in,  p_WinT,  CDIM,   1024, 0);
    tconv_kernel<<<dim3(256/32,  512/32), 256>>>(W_out, p_WoutT, DINNER, 256,  0);
    tconv_kernel<<<dim3(1,       512/32), 256>>>(W_xproj, p_WbcT, DINNER, 48,  16);
    wcombT_kernel<<<DINNER, 256>>>(W_xproj, W_dt);

    // 1. LayerNorm + layout (bf16)
    ln_kernel<<<BATCH*32, 256>>>(x, ln_g, ln_b);

    // 2. G1: xz = xn @ W_in (8192 x 1024 x 256), split u(bf16) / silu(z)(f32)
    gemm_bf16<128,64,32,32,1><<<dim3(1024/64, NROWS/128), 256>>>(
        p_xnh, p_WinT, nullptr, p_uh, p_gz, nullptr, nullptr, CDIM, 0);

    // 3. depthwise conv + silu -> u2 (bf16)
    conv_silu_kernel<<<(NROWS*DINNER)/256, 256>>>(conv_w, conv_b);

    // 4. G2: dtlin = u2 @ wcomb (8192 x 512 x 512), fused softplus + (dt,u2) pack
    gemm_bf16<128,64,32,32,2><<<dim3(DINNER/64, NROWS/128), 256>>>(
        p_u2h, p_wcombT, (float*)p_du, nullptr, nullptr, b_dt, p_u2h, DINNER, 0);

    // 5. G3: bc = u2 @ W_xproj[:,16:48] (8192 x 32 x 512), fused (B,C) pack
    gemm_bf16<128,32,16,32,3><<<dim3(1, NROWS/128), 256>>>(
        p_u2h, p_WbcT, (float*)p_bc, nullptr, nullptr, nullptr, nullptr, DINNER, 0);

    // 6. selective scan + skip + gate -> yg (bf16)
    scan_kernel<<<256, 256>>>(A_log, D_skip);

    // 7. G4: o = yg @ W_out (8192 x 256 x 512)
    gemm_bf16<128,64,32,32,0><<<dim3(CDIM/64, NROWS/128), 256>>>(
        p_ygh, p_WoutT, p_o, nullptr, nullptr, nullptr, nullptr, DINNER, CDIM);

    // 8. transpose + residual
    out_kernel<<<dim3(32, 8, 8), 256>>>(x, out);
}

// round 7
// speedup vs baseline: 1.5297x; 1.5297x over previous
#include <cuda_runtime.h>
#include <cuda_bf16.h>
#include <math.h>
#include <stdint.h>

// ---------------- problem constants ----------------
#define LSEQ   1024
#define BATCH  8
#define CDIM   256
#define DINNER 512
#define DSTATE 16
#define NROWS  (BATCH*LSEQ)   // 8192

typedef __nv_bfloat16 bf16;
typedef __nv_bfloat162 bf162;

// ---------------- scratch (static, no allocs) ----------------
__device__ __align__(256) bf16     g_xnh  [(size_t)NROWS*CDIM];
__device__ __align__(256) bf16     g_uh   [(size_t)NROWS*DINNER];
__device__ __align__(256) bf16     g_gzh  [(size_t)NROWS*DINNER];
__device__ __align__(256) bf16     g_u2h  [(size_t)NROWS*DINNER];
__device__ __align__(256) uint32_t g_du   [(size_t)NROWS*DINNER];  // (dt,u2) bf16 pair
__device__ __align__(256) float2   g_bc   [(size_t)NROWS*DSTATE];
__device__ __align__(256) bf16     g_ygh  [(size_t)NROWS*DINNER];
__device__ __align__(256) float    g_o    [(size_t)NROWS*CDIM];
// weights, bf16, K-major [N][K]
__device__ __align__(256) bf16     g_WinT  [(size_t)1024*CDIM];
__device__ __align__(256) bf16     g_wcombT[(size_t)DINNER*DINNER];
__device__ __align__(256) bf16     g_WbcT  [(size_t)32*DINNER];
__device__ __align__(256) bf16     g_WoutT [(size_t)CDIM*DINNER];

// ---------------- small helpers ----------------
__device__ __forceinline__ float siluf(float v) { return v / (1.f + __expf(-v)); }
__device__ __forceinline__ float softplusf(float v) {
    return (v > 20.f) ? v : log1pf(__expf(v));
}
// pack two floats into bf16x2 word: lo -> bits[0:16), hi -> bits[16:32)
__device__ __forceinline__ uint32_t pbf2(float lo, float hi) {
    uint32_t r;
    asm("cvt.rn.bf16x2.f32 %0, %1, %2;" : "=r"(r) : "f"(hi), "f"(lo));
    return r;
}
__device__ __forceinline__ uint32_t smem_u32(const void* p) {
    return (uint32_t)__cvta_generic_to_shared(p);
}
__device__ __forceinline__ void cp16(uint32_t sm, const void* gm) {
    asm volatile("cp.async.cg.shared.global [%0], [%1], 16;\n" :: "r"(sm), "l"(gm));
}
__device__ __forceinline__ void mma16(float* c, const uint32_t* a, const uint32_t* b) {
    asm volatile(
        "mma.sync.aligned.m16n8k16.row.col.f32.bf16.bf16.f32 "
        "{%0,%1,%2,%3}, {%4,%5,%6,%7}, {%8,%9}, {%0,%1,%2,%3};\n"
        : "+f"(c[0]), "+f"(c[1]), "+f"(c[2]), "+f"(c[3])
        : "r"(a[0]), "r"(a[1]), "r"(a[2]), "r"(a[3]), "r"(b[0]), "r"(b[1]));
}

// ---------------- prep kernels ----------------
__device__ __forceinline__ void tconv_body(const float* src, bf16* dst,
                                           int K, int ldsrc, int coloff,
                                           int n0, int k0, int t) {
    __shared__ float sm[32][33];
    #pragma unroll
    for (int p = 0; p < 4; p++) {
        int ki = p*8 + (t >> 5);
        sm[ki][t & 31] = src[(size_t)(k0+ki)*ldsrc + coloff + n0 + (t & 31)];
    }
    __syncthreads();
    #pragma unroll
    for (int p = 0; p < 4; p++) {
        int ni = p*8 + (t >> 5);
        dst[(size_t)(n0+ni)*K + k0 + (t & 31)] = __float2bfloat16(sm[t & 31][ni]);
    }
}

// prepA: W_in (256x1024) -> WinT[1024][256]
__global__ __launch_bounds__(256) void prepA_kernel(const float* __restrict__ W_in) {
    tconv_body(W_in, g_WinT, CDIM, 1024, 0, blockIdx.x*32, blockIdx.y*32, threadIdx.x);
}

// prepB: WoutT (blocks 0..127), WbcT (128..143), wcombT (144..655)
__global__ __launch_bounds__(256) void prepB_kernel(const float* __restrict__ W_out,
                                                    const float* __restrict__ W_xproj,
                                                    const float* __restrict__ W_dt) {
    int bid = blockIdx.x, t = threadIdx.x;
    if (bid < 128) {
        tconv_body(W_out, g_WoutT, DINNER, 256, 0, (bid & 7)*32, (bid >> 3)*32, t);
    } else if (bid < 144) {
        tconv_body(W_xproj, g_WbcT, DINNER, 48, 16, 0, (bid - 128)*32, t);
    } else {
        __shared__ float wd[16];
        int n = bid - 144;
        if (t < 16) wd[t] = W_dt[t*DINNER + n];
        __syncthreads();
        for (int k = t; k < DINNER; k += 256) {
            float a = 0.f;
            #pragma unroll
            for (int j = 0; j < 16; j++) a = fmaf(wd[j], W_xproj[k*48 + j], a);
            g_wcombT[(size_t)n*DINNER + k] = __float2bfloat16(a);
        }
    }
}

// ---------------- LayerNorm + (B,C,H,W) -> (B,L,C) bf16 ----------------
__global__ __launch_bounds__(256) void ln_kernel(const float* __restrict__ x,
                                                 const float* __restrict__ gamma,
                                                 const float* __restrict__ beta) {
    __shared__ float sm[32*257];
    __shared__ float s_mu[32], s_rs[32];
    const int b  = blockIdx.x >> 5;
    const int l0 = (blockIdx.x & 31) * 32;
    const int t  = threadIdx.x;
    #pragma unroll
    for (int j = 0; j < 32; j++) {
        int e = j*256 + t;
        sm[(e & 31)*257 + (e >> 5)] = x[((size_t)(b*CDIM + (e >> 5)))*LSEQ + l0 + (e & 31)];
    }
    __syncthreads();
    const int w = t >> 5, lane = t & 31;
    #pragma unroll
    for (int q = 0; q < 4; q++) {
        int li = w*4 + q;
        float s = 0.f, s2 = 0.f;
        #pragma unroll
        for (int j = 0; j < 8; j++) {
            float v = sm[li*257 + lane + j*32];
            s += v; s2 = fmaf(v, v, s2);
        }
        #pragma unroll
        for (int o = 16; o; o >>= 1) {
            s  += __shfl_xor_sync(0xffffffffu, s,  o);
            s2 += __shfl_xor_sync(0xffffffffu, s2, o);
        }
        if (lane == 0) {
            float mu = s * (1.f/CDIM);
            s_mu[li] = mu;
            s_rs[li] = rsqrtf(s2 * (1.f/CDIM) - mu*mu + 1e-5f);
        }
    }
    __syncthreads();
    const float g = gamma[t], be = beta[t];
    #pragma unroll
    for (int li = 0; li < 32; li++) {
        float v = (sm[li*257 + t] - s_mu[li]) * s_rs[li];
        g_xnh[((size_t)(b*LSEQ + l0 + li))*CDIM + t] = __float2bfloat16(fmaf(v, g, be));
    }
}

// ---------------- bf16 mma.sync GEMM, 3-stage cp.async, 1 sync/iter ----------------
// A[M][K] bf16 row-major, Bt[N][K] bf16 K-major. 256 threads (8 warps).
// MODE 0: fp32 out -> Cf (ldc)
// MODE 1: col<512 -> u bf16 (g_uh); col>=512 -> silu -> g_gzh
// MODE 2: dt = softplus(v + e0[col]); pack (dt,u2) word -> g_du
// MODE 3: BN=32 (WN=32): g_bc[row*16+s] = (D[s], D[s+16])
template<int BM, int BN, int WM, int WN, int MODE>
__global__ __launch_bounds__(256) void gemm_mma(
    const bf16* __restrict__ A, const bf16* __restrict__ Bt,
    float* __restrict__ Cf, const float* __restrict__ e0,
    int K, int ldc)
{
    constexpr int BK = 32, ST = 3;
    constexpr int LDA = BK + 8;     // 40 bf16 per smem row
    constexpr int LDW = LDA / 2;    // 20 words
    extern __shared__ bf16 sm[];
    bf16* As = sm;                  // ST * BM * LDA
    bf16* Bs = sm + (size_t)ST*BM*LDA;
    const int tid = threadIdx.x, wid = tid >> 5, lane = tid & 31;
    const int g = lane >> 2, q = lane & 3;
    constexpr int NWN = BN / WN;
    const int wm = wid / NWN, wn = wid % NWN;
    const int m0 = blockIdx.y * BM, n0 = blockIdx.x * BN;
    constexpr int MF = WM / 16, NF = WN / 8;
    float acc[MF][NF][4] = {};

    auto load_stage = [&](int s, int kt) {
        const int k0 = kt * BK;
        #pragma unroll
        for (int i = 0; i < BM*4/256; i++) {
            int idx = tid + i*256;
            int r = idx >> 2, c = idx & 3;
            cp16(smem_u32(&As[(s*BM + r)*LDA + c*8]), &A[(size_t)(m0+r)*K + k0 + c*8]);
        }
        #pragma unroll
        for (int i = 0; i < (BN*4 + 255)/256; i++) {
            int idx = tid + i*256;
            if ((BN*4) % 256 == 0 || idx < BN*4) {
                int r = idx >> 2, c = idx & 3;
                cp16(smem_u32(&Bs[(s*BN + r)*LDA + c*8]), &Bt[(size_t)(n0+r)*K + k0 + c*8]);
            }
        }
        asm volatile("cp.async.commit_group;\n");
    };
    auto compute = [&](int s) {
        const uint32_t* A32 = (const uint32_t*)(As + (size_t)s*BM*LDA);
        const uint32_t* B32 = (const uint32_t*)(Bs + (size_t)s*BN*LDA);
        #pragma unroll
        for (int h = 0; h < 2; h++) {
            uint32_t af[MF][4], bfr[NF][2];
            #pragma unroll
            for (int i = 0; i < MF; i++) {
                int r = wm*WM + i*16 + g;
                af[i][0] = A32[(r  )*LDW + h*8 + q];
                af[i][1] = A32[(r+8)*LDW + h*8 + q];
                af[i][2] = A32[(r  )*LDW + h*8 + q + 4];
                af[i][3] = A32[(r+8)*LDW + h*8 + q + 4];
            }
            #pragma unroll
            for (int j = 0; j < NF; j++) {
                int c = wn*WN + j*8 + g;
                bfr[j][0] = B32[c*LDW + h*8 + q];
                bfr[j][1] = B32[c*LDW + h*8 + q + 4];
            }
            #pragma unroll
            for (int i = 0; i < MF; i++)
                #pragma unroll
                for (int j = 0; j < NF; j++)
                    mma16(acc[i][j], af[i], bfr[j]);
        }
    };

    const int nk = K / BK;
    load_stage(0, 0);
    load_stage(1, 1);
    #pragma unroll 1
    for (int kt = 0; kt < nk; kt++) {
        asm volatile("cp.async.wait_group 1;\n");
        __syncthreads();
        int nx = kt + 2;
        if (nx < nk) load_stage(nx % ST, nx);
        else asm volatile("cp.async.commit_group;\n");
        compute(kt % ST);
    }

    // ----- epilogue -----
    #pragma unroll
    for (int i = 0; i < MF; i++) {
        int row = m0 + wm*WM + i*16 + g;
        if (MODE == 3) {
            // BN=32, WN=32: pair col s with s+16 -> g_bc float2
            #pragma unroll
            for (int j = 0; j < 2; j++) {
                int s = j*8 + 2*q;
                float4 lo = make_float4(acc[i][j][0], acc[i][j+2][0],
                                        acc[i][j][1], acc[i][j+2][1]);
                float4 hi = make_float4(acc[i][j][2], acc[i][j+2][2],
                                        acc[i][j][3], acc[i][j+2][3]);
                *(float4*)&g_bc[(size_t)(row  )*DSTATE + s] = lo;
                *(float4*)&g_bc[(size_t)(row+8)*DSTATE + s] = hi;
            }
        } else {
            #pragma unroll
            for (int j = 0; j < NF; j++) {
                int col = n0 + wn*WN + j*8 + 2*q;
                float v0 = acc[i][j][0], v1 = acc[i][j][1];
                float v2 = acc[i][j][2], v3 = acc[i][j][3];
                if (MODE == 0) {
                    *(float2*)&Cf[(size_t)(row  )*ldc + col] = make_float2(v0, v1);
                    *(float2*)&Cf[(size_t)(row+8)*ldc + col] = make_float2(v2, v3);
                } else if (MODE == 1) {
                    if (col < DINNER) {
                        *(uint32_t*)&g_uh[(size_t)(row  )*DINNER + col] = pbf2(v0, v1);
                        *(uint32_t*)&g_uh[(size_t)(row+8)*DINNER + col] = pbf2(v2, v3);
                    } else {
                        int cz = col - DINNER;
                        *(uint32_t*)&g_gzh[(size_t)(row  )*DINNER + cz] =
                            pbf2(siluf(v0), siluf(v1));
                        *(uint32_t*)&g_gzh[(size_t)(row+8)*DINNER + cz] =
                            pbf2(siluf(v2), siluf(v3));
                    }
                } else { // MODE 2
                    float b0 = e0[col], b1 = e0[col+1];
                    uint32_t ua = *(const uint32_t*)&g_u2h[(size_t)(row  )*DINNER + col];
                    uint32_t ub = *(const uint32_t*)&g_u2h[(size_t)(row+8)*DINNER + col];
                    uint32_t d0 = (uint32_t)__bfloat16_as_ushort(__float2bfloat16(softplusf(v0 + b0)));
                    uint32_t d1 = (uint32_t)__bfloat16_as_ushort(__float2bfloat16(softplusf(v1 + b1)));
                    uint32_t d2 = (uint32_t)__bfloat16_as_ushort(__float2bfloat16(softplusf(v2 + b0)));
                    uint32_t d3 = (uint32_t)__bfloat16_as_ushort(__float2bfloat16(softplusf(v3 + b1)));
                    uint2 wa = make_uint2(d0 | ((ua & 0xFFFFu) << 16), d1 | (ua & 0xFFFF0000u));
                    uint2 wb = make_uint2(d2 | ((ub & 0xFFFFu) << 16), d3 | (ub & 0xFFFF0000u));
                    *(uint2*)&g_du[(size_t)(row  )*DINNER + col] = wa;
                    *(uint2*)&g_du[(size_t)(row+8)*DINNER + col] = wb;
                }
            }
        }
    }
}

// ---------------- depthwise causal conv (D_CONV=4) + SiLU, bf162 ----------------
__global__ __launch_bounds__(256) void conv_silu_kernel(const float* __restrict__ cw,
                                                        const float* __restrict__ cb) {
    int gid = blockIdx.x*256 + threadIdx.x;    // over NROWS*256 channel-pairs
    int d2  = gid & 255;
    int row = gid >> 8;
    int l   = row & (LSEQ-1);
    int d   = d2 * 2;
    float a0 = cb[d], a1 = cb[d+1];
    const uint32_t* up = (const uint32_t*)g_uh;
    #pragma unroll
    for (int k = 0; k < 4; k++) {
        int ll = l - 3 + k;
        if (ll >= 0) {
            uint32_t w = up[(size_t)(row - 3 + k)*256 + d2];
            bf162 p = *(bf162*)&w;
            a0 = fmaf(__bfloat162float(p.x), cw[d*4 + k],     a0);
            a1 = fmaf(__bfloat162float(p.y), cw[(d+1)*4 + k], a1);
        }
    }
    ((uint32_t*)g_u2h)[gid] = pbf2(siluf(a0), siluf(a1));
}

// ---------------- selective scan: warp = 2 channels, lane-per-state ----------------
__global__ __launch_bounds__(256) void scan_kernel(const float* __restrict__ A_log,
                                                   const float* __restrict__ D_skip) {
    int gw   = (blockIdx.x * 256 + threadIdx.x) >> 5;   // 0..2047
    int lane = threadIdx.x & 31;
    int b    = gw >> 8;
    int pair = gw & 255;
    int d    = pair*2 + (lane >> 4);
    int s    = lane & 15;
    float Aval = -__expf(A_log[d*DSTATE + s]);
    float Dd   = D_skip[d];
    size_t rb = (size_t)b * LSEQ;
    const uint32_t* duP = g_du  + rb*DINNER + d;
    const float2*   bcP = g_bc  + rb*DSTATE + s;
    const bf16*     gzP = g_gzh + rb*DINNER + d;
    bf16*           ygP = g_ygh + rb*DINNER + d;
    float h = 0.f;
    for (int l = 0; l < LSEQ; l++) {
        uint32_t w = duP[(size_t)l*DINNER];
        bf162 p = *(bf162*)&w;
        float dt = __bfloat162float(p.x);
        float u2 = __bfloat162float(p.y);
        float2 bcv = bcP[(size_t)l*DSTATE];
        float dA = __expf(dt * Aval);
        h = fmaf(dA, h, dt * u2 * bcv.x);
        float pr = h * bcv.y;
        pr += __shfl_xor_sync(0xffffffffu, pr, 8);
        pr += __shfl_xor_sync(0xffffffffu, pr, 4);
        pr += __shfl_xor_sync(0xffffffffu, pr, 2);
        pr += __shfl_xor_sync(0xffffffffu, pr, 1);
        if (s == 0) {
            float yv = pr + u2 * Dd;
            ygP[(size_t)l*DINNER] =
                __float2bfloat16(yv * __bfloat162float(gzP[(size_t)l*DINNER]));
        }
    }
}

// ---------------- o(B,L,C) -> out(B,C,H,W) + residual x ----------------
__global__ __launch_bounds__(256) void out_kernel(const float* __restrict__ x,
                                                  float* __restrict__ out) {
    __shared__ float sm[32][33];
    const int b  = blockIdx.z;
    const int c0 = blockIdx.y * 32;
    const int l0 = blockIdx.x * 32;
    const int t  = threadIdx.x;
    const int ci = t & 31, lq = t >> 5;
    #pragma unroll
    for (int p = 0; p < 4; p++) {
        int li = p*8 + lq;
        sm[li][ci] = g_o[((size_t)(b*LSEQ + l0 + li))*CDIM + c0 + ci];
    }
    __syncthreads();
    const int li2 = t & 31, cq = t >> 5;
    #pragma unroll
    for (int p = 0; p < 4; p++) {
        int ci2 = p*8 + cq;
        size_t idx = ((size_t)(b*CDIM + c0 + ci2))*LSEQ + l0 + li2;
        out[idx] = sm[li2][ci2] + x[idx];
    }
}

// ---------------- host launch ----------------
extern "C" void kernel_launch(void* const* d_in, const int* in_sizes, int n_in,
                              void* d_out, int out_size) {
    const float* x       = (const float*)d_in[0];
    const float* ln_g    = (const float*)d_in[1];
    const float* ln_b    = (const float*)d_in[2];
    const float* W_in    = (const float*)d_in[3];
    const float* conv_w  = (const float*)d_in[4];
    const float* conv_b  = (const float*)d_in[5];
    const float* W_xproj = (const float*)d_in[6];
    const float* W_dt    = (const float*)d_in[7];
    const float* b_dt    = (const float*)d_in[8];
    const float* A_log   = (const float*)d_in[9];
    const float* D_skip  = (const float*)d_in[10];
    const float* W_out   = (const float*)d_in[11];
    float* out = (float*)d_out;

    bf16 *p_xnh, *p_u2h, *p_ygh, *p_WinT, *p_wcombT, *p_WbcT, *p_WoutT;
    float *p_o;
    cudaGetSymbolAddress((void**)&p_xnh,    g_xnh);
    cudaGetSymbolAddress((void**)&p_u2h,    g_u2h);
    cudaGetSymbolAddress((void**)&p_ygh,    g_ygh);
    cudaGetSymbolAddress((void**)&p_o,      g_o);
    cudaGetSymbolAddress((void**)&p_WinT,   g_WinT);
    cudaGetSymbolAddress((void**)&p_wcombT, g_wcombT);
    cudaGetSymbolAddress((void**)&p_WbcT,   g_WbcT);
    cudaGetSymbolAddress((void**)&p_WoutT,  g_WoutT);

    // dynamic smem: 3 stages * (BM+BN) rows * 40 bf16
    const int SMB128 = 3*(128+128)*40*2;   // 61440
    const int SMB32  = 3*(128+32)*40*2;    // 38400
    cudaFuncSetAttribute(gemm_mma<128,128,64,32,0>, cudaFuncAttributeMaxDynamicSharedMemorySize, SMB128);
    cudaFuncSetAttribute(gemm_mma<128,128,64,32,1>, cudaFuncAttributeMaxDynamicSharedMemorySize, SMB128);
    cudaFuncSetAttribute(gemm_mma<128,128,64,32,2>, cudaFuncAttributeMaxDynamicSharedMemorySize, SMB128);
    cudaFuncSetAttribute(gemm_mma<128,32,16,32,3>,  cudaFuncAttributeMaxDynamicSharedMemorySize, SMB32);

    // launch index:                                   (ncu captures index 3)
    prepA_kernel<<<dim3(32, 8), 256>>>(W_in);                          // 0
    prepB_kernel<<<656, 256>>>(W_out, W_xproj, W_dt);                  // 1
    ln_kernel<<<BATCH*32, 256>>>(x, ln_g, ln_b);                       // 2
    // G1: xn @ W_in (8192 x 1024 x 256) -> u bf16 / silu(z) bf16
    gemm_mma<128,128,64,32,1><<<dim3(8, 64), 256, SMB128>>>(           // 3
        p_xnh, p_WinT, nullptr, nullptr, CDIM, 0);
    conv_silu_kernel<<<NROWS, 256>>>(conv_w, conv_b);                  // 4
    // G2: u2 @ wcomb (8192 x 512 x 512) -> (dt,u2) packed
    gemm_mma<128,128,64,32,2><<<dim3(4, 64), 256, SMB128>>>(           // 5
        p_u2h, p_wcombT, nullptr, b_dt, DINNER, 0);
    // G3: u2 @ Wbc (8192 x 32 x 512) -> (B,C) packed
    gemm_mma<128,32,16,32,3><<<dim3(1, 64), 256, SMB32>>>(             // 6
        p_u2h, p_WbcT, nullptr, nullptr, DINNER, 0);
    scan_kernel<<<256, 256>>>(A_log, D_skip);                          // 7
    // G4: yg @ W_out (8192 x 256 x 512) -> o fp32
    gemm_mma<128,128,64,32,0><<<dim3(2, 64), 256, SMB128>>>(           // 8
        p_ygh, p_WoutT, p_o, nullptr, DINNER, CDIM);
    out_kernel<<<dim3(32, 8, 8), 256>>>(x, out);                       // 9
}

// round 8
// speedup vs baseline: 1.9548x; 1.2779x over previous
#include <cuda_runtime.h>
#include <cuda_bf16.h>
#include <math.h>
#include <stdint.h>

// ---------------- problem constants ----------------
#define LSEQ   1024
#define BATCH  8
#define CDIM   256
#define DINNER 512
#define DSTATE 16
#define NROWS  (BATCH*LSEQ)   // 8192

typedef __nv_bfloat16 bf16;
typedef __nv_bfloat162 bf162;

// ---------------- scratch (static, no allocs) ----------------
__device__ __align__(256) bf16     g_xnh  [(size_t)NROWS*CDIM];
__device__ __align__(256) bf16     g_uh   [(size_t)NROWS*DINNER];
__device__ __align__(256) unsigned short g_gz2[(size_t)DINNER*NROWS]; // silu(z) bf16, [d][row]
__device__ __align__(256) bf16     g_u2h  [(size_t)NROWS*DINNER];
__device__ __align__(256) uint32_t g_du   [(size_t)DINNER*NROWS];    // (dt,u2) pack, [d][row]
__device__ __align__(256) float2   g_bc   [(size_t)NROWS*DSTATE];    // [row][s]
__device__ __align__(256) bf16     g_ygh  [(size_t)NROWS*DINNER];    // [row][d]
__device__ __align__(256) float    g_o    [(size_t)NROWS*CDIM];
// weights, bf16, K-major [N][K]
__device__ __align__(256) bf16     g_WinT  [(size_t)1024*CDIM];
__device__ __align__(256) bf16     g_wcombT[(size_t)DINNER*DINNER];
__device__ __align__(256) bf16     g_WbcT  [(size_t)32*DINNER];
__device__ __align__(256) bf16     g_WoutT [(size_t)CDIM*DINNER];

// ---------------- small helpers ----------------
__device__ __forceinline__ float siluf(float v) { return v / (1.f + __expf(-v)); }
__device__ __forceinline__ float softplusf(float v) {
    return (v > 20.f) ? v : log1pf(__expf(v));
}
__device__ __forceinline__ uint32_t pbf2(float lo, float hi) {
    uint32_t r;
    asm("cvt.rn.bf16x2.f32 %0, %1, %2;" : "=r"(r) : "f"(hi), "f"(lo));
    return r;
}
__device__ __forceinline__ uint32_t smem_u32(const void* p) {
    return (uint32_t)__cvta_generic_to_shared(p);
}
__device__ __forceinline__ void cp16(uint32_t sm, const void* gm) {
    asm volatile("cp.async.cg.shared.global [%0], [%1], 16;\n" :: "r"(sm), "l"(gm));
}
__device__ __forceinline__ void mma16(float* c, const uint32_t* a, const uint32_t* b) {
    asm volatile(
        "mma.sync.aligned.m16n8k16.row.col.f32.bf16.bf16.f32 "
        "{%0,%1,%2,%3}, {%4,%5,%6,%7}, {%8,%9}, {%0,%1,%2,%3};\n"
        : "+f"(c[0]), "+f"(c[1]), "+f"(c[2]), "+f"(c[3])
        : "r"(a[0]), "r"(a[1]), "r"(a[2]), "r"(a[3]), "r"(b[0]), "r"(b[1]));
}

// ---------------- prep kernels ----------------
__device__ __forceinline__ void tconv_body(const float* src, bf16* dst,
                                           int K, int ldsrc, int coloff,
                                           int n0, int k0, int t) {
    __shared__ float sm[32][33];
    #pragma unroll
    for (int p = 0; p < 4; p++) {
        int ki = p*8 + (t >> 5);
        sm[ki][t & 31] = src[(size_t)(k0+ki)*ldsrc + coloff + n0 + (t & 31)];
    }
    __syncthreads();
    #pragma unroll
    for (int p = 0; p < 4; p++) {
        int ni = p*8 + (t >> 5);
        dst[(size_t)(n0+ni)*K + k0 + (t & 31)] = __float2bfloat16(sm[t & 31][ni]);
    }
}

__global__ __launch_bounds__(256) void prepA_kernel(const float* __restrict__ W_in) {
    tconv_body(W_in, g_WinT, CDIM, 1024, 0, blockIdx.x*32, blockIdx.y*32, threadIdx.x);
}

__global__ __launch_bounds__(256) void prepB_kernel(const float* __restrict__ W_out,
                                                    const float* __restrict__ W_xproj,
                                                    const float* __restrict__ W_dt) {
    int bid = blockIdx.x, t = threadIdx.x;
    if (bid < 128) {
        tconv_body(W_out, g_WoutT, DINNER, 256, 0, (bid & 7)*32, (bid >> 3)*32, t);
    } else if (bid < 144) {
        tconv_body(W_xproj, g_WbcT, DINNER, 48, 16, 0, (bid - 128)*32, t);
    } else {
        __shared__ float wd[16];
        int n = bid - 144;
        if (t < 16) wd[t] = W_dt[t*DINNER + n];
        __syncthreads();
        for (int k = t; k < DINNER; k += 256) {
            float a = 0.f;
            #pragma unroll
            for (int j = 0; j < 16; j++) a = fmaf(wd[j], W_xproj[k*48 + j], a);
            g_wcombT[(size_t)n*DINNER + k] = __float2bfloat16(a);
        }
    }
}

// ---------------- LayerNorm + (B,C,H,W) -> (B,L,C) bf16 ----------------
__global__ __launch_bounds__(256) void ln_kernel(const float* __restrict__ x,
                                                 const float* __restrict__ gamma,
                                                 const float* __restrict__ beta) {
    __shared__ float sm[32*257];
    __shared__ float s_mu[32], s_rs[32];
    const int b  = blockIdx.x >> 5;
    const int l0 = (blockIdx.x & 31) * 32;
    const int t  = threadIdx.x;
    #pragma unroll
    for (int j = 0; j < 32; j++) {
        int e = j*256 + t;
        sm[(e & 31)*257 + (e >> 5)] = x[((size_t)(b*CDIM + (e >> 5)))*LSEQ + l0 + (e & 31)];
    }
    __syncthreads();
    const int w = t >> 5, lane = t & 31;
    #pragma unroll
    for (int q = 0; q < 4; q++) {
        int li = w*4 + q;
        float s = 0.f, s2 = 0.f;
        #pragma unroll
        for (int j = 0; j < 8; j++) {
            float v = sm[li*257 + lane + j*32];
            s += v; s2 = fmaf(v, v, s2);
        }
        #pragma unroll
        for (int o = 16; o; o >>= 1) {
            s  += __shfl_xor_sync(0xffffffffu, s,  o);
            s2 += __shfl_xor_sync(0xffffffffu, s2, o);
        }
        if (lane == 0) {
            float mu = s * (1.f/CDIM);
            s_mu[li] = mu;
            s_rs[li] = rsqrtf(s2 * (1.f/CDIM) - mu*mu + 1e-5f);
        }
    }
    __syncthreads();
    const float g = gamma[t], be = beta[t];
    #pragma unroll
    for (int li = 0; li < 32; li++) {
        float v = (sm[li*257 + t] - s_mu[li]) * s_rs[li];
        g_xnh[((size_t)(b*LSEQ + l0 + li))*CDIM + t] = __float2bfloat16(fmaf(v, g, be));
    }
}

// ---------------- bf16 mma.sync GEMM, 3-stage cp.async, 1 sync/iter ----------------
// MODE 0: fp32 out -> Cf (ldc)
// MODE 1: col<512 -> u bf16 (g_uh row-major); col>=512 -> silu -> g_gz2 [d][row]
// MODE 2: dt = softplus(v + e0[col]); pack (dt,u2) -> g_du [d][row]
// MODE 3: BN=32 (WN=32): g_bc[row*16+s] = (D[s], D[s+16])
template<int BM, int BN, int WM, int WN, int MODE>
__global__ __launch_bounds__(256) void gemm_mma(
    const bf16* __restrict__ A, const bf16* __restrict__ Bt,
    float* __restrict__ Cf, const float* __restrict__ e0,
    int K, int ldc)
{
    constexpr int BK = 32, ST = 3;
    constexpr int LDA = BK + 8;
    constexpr int LDW = LDA / 2;
    extern __shared__ bf16 sm[];
    bf16* As = sm;
    bf16* Bs = sm + (size_t)ST*BM*LDA;
    const int tid = threadIdx.x, wid = tid >> 5, lane = tid & 31;
    const int g = lane >> 2, q = lane & 3;
    constexpr int NWN = BN / WN;
    const int wm = wid / NWN, wn = wid % NWN;
    const int m0 = blockIdx.y * BM, n0 = blockIdx.x * BN;
    constexpr int MF = WM / 16, NF = WN / 8;
    float acc[MF][NF][4] = {};

    auto load_stage = [&](int s, int kt) {
        const int k0 = kt * BK;
        #pragma unroll
        for (int i = 0; i < BM*4/256; i++) {
            int idx = tid + i*256;
            int r = idx >> 2, c = idx & 3;
            cp16(smem_u32(&As[(s*BM + r)*LDA + c*8]), &A[(size_t)(m0+r)*K + k0 + c*8]);
        }
        #pragma unroll
        for (int i = 0; i < (BN*4 + 255)/256; i++) {
            int idx = tid + i*256;
            if ((BN*4) % 256 == 0 || idx < BN*4) {
                int r = idx >> 2, c = idx & 3;
                cp16(smem_u32(&Bs[(s*BN + r)*LDA + c*8]), &Bt[(size_t)(n0+r)*K + k0 + c*8]);
            }
        }
        asm volatile("cp.async.commit_group;\n");
    };
    auto compute = [&](int s) {
        const uint32_t* A32 = (const uint32_t*)(As + (size_t)s*BM*LDA);
        const uint32_t* B32 = (const uint32_t*)(Bs + (size_t)s*BN*LDA);
        #pragma unroll
        for (int h = 0; h < 2; h++) {
            uint32_t af[MF][4], bfr[NF][2];
            #pragma unroll
            for (int i = 0; i < MF; i++) {
                int r = wm*WM + i*16 + g;
                af[i][0] = A32[(r  )*LDW + h*8 + q];
                af[i][1] = A32[(r+8)*LDW + h*8 + q];
                af[i][2] = A32[(r  )*LDW + h*8 + q + 4];
                af[i][3] = A32[(r+8)*LDW + h*8 + q + 4];
            }
            #pragma unroll
            for (int j = 0; j < NF; j++) {
                int c = wn*WN + j*8 + g;
                bfr[j][0] = B32[c*LDW + h*8 + q];
                bfr[j][1] = B32[c*LDW + h*8 + q + 4];
            }
            #pragma unroll
            for (int i = 0; i < MF; i++)
                #pragma unroll
                for (int j = 0; j < NF; j++)
                    mma16(acc[i][j], af[i], bfr[j]);
        }
    };

    const int nk = K / BK;
    load_stage(0, 0);
    load_stage(1, 1);
    #pragma unroll 1
    for (int kt = 0; kt < nk; kt++) {
        asm volatile("cp.async.wait_group 1;\n");
        __syncthreads();
        int nx = kt + 2;
        if (nx < nk) load_stage(nx % ST, nx);
        else asm volatile("cp.async.commit_group;\n");
        compute(kt % ST);
    }

    // ----- epilogue -----
    #pragma unroll
    for (int i = 0; i < MF; i++) {
        int row = m0 + wm*WM + i*16 + g;
        if (MODE == 3) {
            #pragma unroll
            for (int j = 0; j < 2; j++) {
                int s = j*8 + 2*q;
                float4 lo = make_float4(acc[i][j][0], acc[i][j+2][0],
                                        acc[i][j][1], acc[i][j+2][1]);
                float4 hi = make_float4(acc[i][j][2], acc[i][j+2][2],
                                        acc[i][j][3], acc[i][j+2][3]);
                *(float4*)&g_bc[(size_t)(row  )*DSTATE + s] = lo;
                *(float4*)&g_bc[(size_t)(row+8)*DSTATE + s] = hi;
            }
        } else {
            #pragma unroll
            for (int j = 0; j < NF; j++) {
                int col = n0 + wn*WN + j*8 + 2*q;
                float v0 = acc[i][j][0], v1 = acc[i][j][1];
                float v2 = acc[i][j][2], v3 = acc[i][j][3];
                if (MODE == 0) {
                    *(float2*)&Cf[(size_t)(row  )*ldc + col] = make_float2(v0, v1);
                    *(float2*)&Cf[(size_t)(row+8)*ldc + col] = make_float2(v2, v3);
                } else if (MODE == 1) {
                    if (col < DINNER) {
                        *(uint32_t*)&g_uh[(size_t)(row  )*DINNER + col] = pbf2(v0, v1);
                        *(uint32_t*)&g_uh[(size_t)(row+8)*DINNER + col] = pbf2(v2, v3);
                    } else {
                        int cz = col - DINNER;
                        g_gz2[(size_t)cz    *NROWS + row  ] = __bfloat16_as_ushort(__float2bfloat16(siluf(v0)));
                        g_gz2[(size_t)(cz+1)*NROWS + row  ] = __bfloat16_as_ushort(__float2bfloat16(siluf(v1)));
                        g_gz2[(size_t)cz    *NROWS + row+8] = __bfloat16_as_ushort(__float2bfloat16(siluf(v2)));
                        g_gz2[(size_t)(cz+1)*NROWS + row+8] = __bfloat16_as_ushort(__float2bfloat16(siluf(v3)));
                    }
                } else { // MODE 2: transposed (dt,u2) pack -> g_du[d][row]
                    float b0 = e0[col], b1 = e0[col+1];
                    uint32_t ua = *(const uint32_t*)&g_u2h[(size_t)(row  )*DINNER + col];
                    uint32_t ub = *(const uint32_t*)&g_u2h[(size_t)(row+8)*DINNER + col];
                    uint32_t d0 = (uint32_t)__bfloat16_as_ushort(__float2bfloat16(softplusf(v0 + b0)));
                    uint32_t d1 = (uint32_t)__bfloat16_as_ushort(__float2bfloat16(softplusf(v1 + b1)));
                    uint32_t d2 = (uint32_t)__bfloat16_as_ushort(__float2bfloat16(softplusf(v2 + b0)));
                    uint32_t d3 = (uint32_t)__bfloat16_as_ushort(__float2bfloat16(softplusf(v3 + b1)));
                    g_du[(size_t)col    *NROWS + row  ] = d0 | ((ua & 0xFFFFu) << 16);
                    g_du[(size_t)(col+1)*NROWS + row  ] = d1 | (ua & 0xFFFF0000u);
                    g_du[(size_t)col    *NROWS + row+8] = d2 | ((ub & 0xFFFFu) << 16);
                    g_du[(size_t)(col+1)*NROWS + row+8] = d3 | (ub & 0xFFFF0000u);
                }
            }
        }
    }
}

// ---------------- depthwise causal conv (D_CONV=4) + SiLU, bf162 ----------------
__global__ __launch_bounds__(256) void conv_silu_kernel(const float* __restrict__ cw,
                                                        const float* __restrict__ cb) {
    int gid = blockIdx.x*256 + threadIdx.x;
    int d2  = gid & 255;
    int row = gid >> 8;
    int l   = row & (LSEQ-1);
    int d   = d2 * 2;
    float a0 = cb[d], a1 = cb[d+1];
    const uint32_t* up = (const uint32_t*)g_uh;
    #pragma unroll
    for (int k = 0; k < 4; k++) {
        int ll = l - 3 + k;
        if (ll >= 0) {
            uint32_t w = up[(size_t)(row - 3 + k)*256 + d2];
            bf162 p = *(bf162*)&w;
            a0 = fmaf(__bfloat162float(p.x), cw[d*4 + k],     a0);
            a1 = fmaf(__bfloat162float(p.y), cw[(d+1)*4 + k], a1);
        }
    }
    ((uint32_t*)g_u2h)[gid] = pbf2(siluf(a0), siluf(a1));
}

// ---------------- selective scan v2: coalesced chunked, smem-staged ----------------
// block = 256 thr = 8 warps; covers batch b = blockIdx>>5, 16 channels dblk..dblk+15.
// warp handles 2 chains (half = lane>>4); 16-lane group = states s=0..15.
// Chunked by 16 l: coalesced du/gz loads + shfl broadcast; bc staged in smem;
// yg staged in smem, flushed coalesced.
__global__ __launch_bounds__(256) void scan_kernel(const float* __restrict__ A_log,
                                                   const float* __restrict__ D_skip) {
    __shared__ float2 s_bc[16][16];
    __shared__ unsigned short s_yg[16][16];
    const int b    = blockIdx.x >> 5;
    const int dblk = (blockIdx.x & 31) * 16;
    const int tid  = threadIdx.x;
    const int widx = tid >> 5, lane = tid & 31;
    const int half = lane >> 4, s = lane & 15;
    const int d    = dblk + 2*widx + half;
    const float Aval = -__expf(A_log[d*DSTATE + s]);
    const float Dd   = D_skip[d];
    const size_t rb  = (size_t)b * LSEQ;
    const uint32_t*       duP = g_du  + (size_t)d*NROWS + rb;
    const unsigned short* gzP = g_gz2 + (size_t)d*NROWS + rb;
    const float2*         bcP = g_bc  + rb*DSTATE;
    const int li = tid >> 4, dd = tid & 15;    // fill/flush mapping
    float h = 0.f;
    #pragma unroll 1
    for (int c0 = 0; c0 < LSEQ; c0 += 16) {
        // per-lane chunk loads (coalesced 64B / 32B per 16-lane group)
        uint32_t duw = duP[c0 + s];
        uint32_t gzw = (uint32_t)gzP[c0 + s];
        float2 bcl = bcP[(size_t)(c0 + li)*DSTATE + dd];
        s_bc[li][dd] = bcl;
        __syncthreads();
        #pragma unroll
        for (int j = 0; j < 16; j++) {
            uint32_t w = __shfl_sync(0xffffffffu, duw, j, 16);
            bf162 p = *(bf162*)&w;
            float dt = __bfloat162float(p.x);
            float u2 = __bfloat162float(p.y);
            float2 bcv = s_bc[j][s];
            float dA = __expf(dt * Aval);
            h = fmaf(dA, h, dt * u2 * bcv.x);
            float pr = h * bcv.y;
            pr += __shfl_xor_sync(0xffffffffu, pr, 8);
            pr += __shfl_xor_sync(0xffffffffu, pr, 4);
            pr += __shfl_xor_sync(0xffffffffu, pr, 2);
            pr += __shfl_xor_sync(0xffffffffu, pr, 1);
            uint32_t gj = __shfl_sync(0xffffffffu, gzw, j, 16);
            if (s == 0) {
                float yv = pr + u2 * Dd;
                unsigned short gs = (unsigned short)gj;
                float gzf = __bfloat162float(__ushort_as_bfloat16(gs));
                s_yg[j][2*widx + half] =
                    __bfloat16_as_ushort(__float2bfloat16(yv * gzf));
            }
        }
        __syncthreads();
        ((unsigned short*)g_ygh)[(rb + c0 + li)*DINNER + dblk + dd] = s_yg[li][dd];
    }
}

// ---------------- o(B,L,C) -> out(B,C,H,W) + residual x ----------------
__global__ __launch_bounds__(256) void out_kernel(const float* __restrict__ x,
                                                  float* __restrict__ out) {
    __shared__ float sm[32][33];
    const int b  = blockIdx.z;
    const int c0 = blockIdx.y * 32;
    const int l0 = blockIdx.x * 32;
    const int t  = threadIdx.x;
    const int ci = t & 31, lq = t >> 5;
    #pragma unroll
    for (int p = 0; p < 4; p++) {
        int li = p*8 + lq;
        sm[li][ci] = g_o[((size_t)(b*LSEQ + l0 + li))*CDIM + c0 + ci];
    }
    __syncthreads();
    const int li2 = t & 31, cq = t >> 5;
    #pragma unroll
    for (int p = 0; p < 4; p++) {
        int ci2 = p*8 + cq;
        size_t idx = ((size_t)(b*CDIM + c0 + ci2))*LSEQ + l0 + li2;
        out[idx] = sm[li2][ci2] + x[idx];
    }
}

// ---------------- host launch ----------------
extern "C" void kernel_launch(void* const* d_in, const int* in_sizes, int n_in,
                              void* d_out, int out_size) {
    const float* x       = (const float*)d_in[0];
    const float* ln_g    = (const float*)d_in[1];
    const float* ln_b    = (const float*)d_in[2];
    const float* W_in    = (const float*)d_in[3];
    const float* conv_w  = (const float*)d_in[4];
    const float* conv_b  = (const float*)d_in[5];
    const float* W_xproj = (const float*)d_in[6];
    const float* W_dt    = (const float*)d_in[7];
    const float* b_dt    = (const float*)d_in[8];
    const float* A_log   = (const float*)d_in[9];
    const float* D_skip  = (const float*)d_in[10];
    const float* W_out   = (const float*)d_in[11];
    float* out = (float*)d_out;

    bf16 *p_xnh, *p_u2h, *p_ygh, *p_WinT, *p_wcombT, *p_WbcT, *p_WoutT;
    float *p_o;
    cudaGetSymbolAddress((void**)&p_xnh,    g_xnh);
    cudaGetSymbolAddress((void**)&p_u2h,    g_u2h);
    cudaGetSymbolAddress((void**)&p_ygh,    g_ygh);
    cudaGetSymbolAddress((void**)&p_o,      g_o);
    cudaGetSymbolAddress((void**)&p_WinT,   g_WinT);
    cudaGetSymbolAddress((void**)&p_wcombT, g_wcombT);
    cudaGetSymbolAddress((void**)&p_WbcT,   g_WbcT);
    cudaGetSymbolAddress((void**)&p_WoutT,  g_WoutT);

    const int SMB128 = 3*(128+128)*40*2;   // 61440
    const int SMB32  = 3*(128+32)*40*2;    // 38400
    cudaFuncSetAttribute(gemm_mma<128,128,64,32,0>, cudaFuncAttributeMaxDynamicSharedMemorySize, SMB128);
    cudaFuncSetAttribute(gemm_mma<128,128,64,32,1>, cudaFuncAttributeMaxDynamicSharedMemorySize, SMB128);
    cudaFuncSetAttribute(gemm_mma<128,128,64,32,2>, cudaFuncAttributeMaxDynamicSharedMemorySize, SMB128);
    cudaFuncSetAttribute(gemm_mma<128,32,16,32,3>,  cudaFuncAttributeMaxDynamicSharedMemorySize, SMB32);

    // launch index:                                   (ncu captures index 3)
    prepA_kernel<<<dim3(32, 8), 256>>>(W_in);                          // 0
    prepB_kernel<<<656, 256>>>(W_out, W_xproj, W_dt);                  // 1
    ln_kernel<<<BATCH*32, 256>>>(x, ln_g, ln_b);                       // 2
    gemm_mma<128,128,64,32,1><<<dim3(8, 64), 256, SMB128>>>(           // 3  G1
        p_xnh, p_WinT, nullptr, nullptr, CDIM, 0);
    conv_silu_kernel<<<NROWS, 256>>>(conv_w, conv_b);                  // 4
    gemm_mma<128,128,64,32,2><<<dim3(4, 64), 256, SMB128>>>(           // 5  G2
        p_u2h, p_wcombT, nullptr, b_dt, DINNER, 0);
    gemm_mma<128,32,16,32,3><<<dim3(1, 64), 256, SMB32>>>(             // 6  G3
        p_u2h, p_WbcT, nullptr, nullptr, DINNER, 0);
    scan_kernel<<<256, 256>>>(A_log, D_skip);                          // 7
    gemm_mma<128,128,64,32,0><<<dim3(2, 64), 256, SMB128>>>(           // 8  G4
        p_ygh, p_WoutT, p_o, nullptr, DINNER, CDIM);
    out_kernel<<<dim3(32, 8, 8), 256>>>(x, out);                       // 9
}

// round 9
// speedup vs baseline: 2.9986x; 1.5340x over previous
#include <cuda_runtime.h>
#include <cuda_bf16.h>
#include <math.h>
#include <stdint.h>

// ---------------- problem constants ----------------
#define LSEQ   1024
#define BATCH  8
#define CDIM   256
#define DINNER 512
#define DSTATE 16
#define NROWS  (BATCH*LSEQ)   // 8192

typedef __nv_bfloat16 bf16;
typedef __nv_bfloat162 bf162;

// ---------------- scratch (static, no allocs) ----------------
__device__ __align__(256) bf16     g_xnh  [(size_t)NROWS*CDIM];
__device__ __align__(256) bf16     g_uh   [(size_t)NROWS*DINNER];
__device__ __align__(256) bf16     g_gzh  [(size_t)NROWS*DINNER];   // silu(z), [row][d]
__device__ __align__(256) bf16     g_u2h  [(size_t)NROWS*DINNER];
__device__ __align__(256) uint32_t g_du   [(size_t)NROWS*DINNER];   // (dt,u2) pack, [row][d]
__device__ __align__(256) float2   g_bc   [(size_t)NROWS*DSTATE];   // [row][s]
__device__ __align__(256) bf16     g_ygh  [(size_t)NROWS*DINNER];   // [row][d]
__device__ __align__(256) float    g_o    [(size_t)NROWS*CDIM];
// weights, bf16, K-major [N][K]
__device__ __align__(256) bf16     g_WinT  [(size_t)1024*CDIM];
__device__ __align__(256) bf16     g_wcombT[(size_t)DINNER*DINNER];
__device__ __align__(256) bf16     g_WbcT  [(size_t)32*DINNER];
__device__ __align__(256) bf16     g_WoutT [(size_t)CDIM*DINNER];

// ---------------- small helpers ----------------
__device__ __forceinline__ float siluf(float v) { return v / (1.f + __expf(-v)); }
__device__ __forceinline__ float softplusf(float v) {
    return (v > 20.f) ? v : log1pf(__expf(v));
}
__device__ __forceinline__ uint32_t pbf2(float lo, float hi) {
    uint32_t r;
    asm("cvt.rn.bf16x2.f32 %0, %1, %2;" : "=r"(r) : "f"(hi), "f"(lo));
    return r;
}
__device__ __forceinline__ uint32_t smem_u32(const void* p) {
    return (uint32_t)__cvta_generic_to_shared(p);
}
__device__ __forceinline__ void cp16(uint32_t sm, const void* gm) {
    asm volatile("cp.async.cg.shared.global [%0], [%1], 16;\n" :: "r"(sm), "l"(gm));
}
__device__ __forceinline__ void mma16(float* c, const uint32_t* a, const uint32_t* b) {
    asm volatile(
        "mma.sync.aligned.m16n8k16.row.col.f32.bf16.bf16.f32 "
        "{%0,%1,%2,%3}, {%4,%5,%6,%7}, {%8,%9}, {%0,%1,%2,%3};\n"
        : "+f"(c[0]), "+f"(c[1]), "+f"(c[2]), "+f"(c[3])
        : "r"(a[0]), "r"(a[1]), "r"(a[2]), "r"(a[3]), "r"(b[0]), "r"(b[1]));
}

// ---------------- prep kernels ----------------
__device__ __forceinline__ void tconv_body(const float* src, bf16* dst,
                                           int K, int ldsrc, int coloff,
                                           int n0, int k0, int t) {
    __shared__ float sm[32][33];
    #pragma unroll
    for (int p = 0; p < 4; p++) {
        int ki = p*8 + (t >> 5);
        sm[ki][t & 31] = src[(size_t)(k0+ki)*ldsrc + coloff + n0 + (t & 31)];
    }
    __syncthreads();
    #pragma unroll
    for (int p = 0; p < 4; p++) {
        int ni = p*8 + (t >> 5);
        dst[(size_t)(n0+ni)*K + k0 + (t & 31)] = __float2bfloat16(sm[t & 31][ni]);
    }
}

__global__ __launch_bounds__(256) void prepA_kernel(const float* __restrict__ W_in) {
    tconv_body(W_in, g_WinT, CDIM, 1024, 0, blockIdx.x*32, blockIdx.y*32, threadIdx.x);
}

__global__ __launch_bounds__(256) void prepB_kernel(const float* __restrict__ W_out,
                                                    const float* __restrict__ W_xproj,
                                                    const float* __restrict__ W_dt) {
    int bid = blockIdx.x, t = threadIdx.x;
    if (bid < 128) {
        tconv_body(W_out, g_WoutT, DINNER, 256, 0, (bid & 7)*32, (bid >> 3)*32, t);
    } else if (bid < 144) {
        tconv_body(W_xproj, g_WbcT, DINNER, 48, 16, 0, (bid - 128)*32, t);
    } else {
        __shared__ float wd[16];
        int n = bid - 144;
        if (t < 16) wd[t] = W_dt[t*DINNER + n];
        __syncthreads();
        for (int k = t; k < DINNER; k += 256) {
            float a = 0.f;
            #pragma unroll
            for (int j = 0; j < 16; j++) a = fmaf(wd[j], W_xproj[k*48 + j], a);
            g_wcombT[(size_t)n*DINNER + k] = __float2bfloat16(a);
        }
    }
}

// ---------------- LayerNorm + (B,C,H,W) -> (B,L,C) bf16 ----------------
__global__ __launch_bounds__(256) void ln_kernel(const float* __restrict__ x,
                                                 const float* __restrict__ gamma,
                                                 const float* __restrict__ beta) {
    __shared__ float sm[32*257];
    __shared__ float s_mu[32], s_rs[32];
    const int b  = blockIdx.x >> 5;
    const int l0 = (blockIdx.x & 31) * 32;
    const int t  = threadIdx.x;
    #pragma unroll
    for (int j = 0; j < 32; j++) {
        int e = j*256 + t;
        sm[(e & 31)*257 + (e >> 5)] = x[((size_t)(b*CDIM + (e >> 5)))*LSEQ + l0 + (e & 31)];
    }
    __syncthreads();
    const int w = t >> 5, lane = t & 31;
    #pragma unroll
    for (int q = 0; q < 4; q++) {
        int li = w*4 + q;
        float s = 0.f, s2 = 0.f;
        #pragma unroll
        for (int j = 0; j < 8; j++) {
            float v = sm[li*257 + lane + j*32];
            s += v; s2 = fmaf(v, v, s2);
        }
        #pragma unroll
        for (int o = 16; o; o >>= 1) {
            s  += __shfl_xor_sync(0xffffffffu, s,  o);
            s2 += __shfl_xor_sync(0xffffffffu, s2, o);
        }
        if (lane == 0) {
            float mu = s * (1.f/CDIM);
            s_mu[li] = mu;
            s_rs[li] = rsqrtf(s2 * (1.f/CDIM) - mu*mu + 1e-5f);
        }
    }
    __syncthreads();
    const float g = gamma[t], be = beta[t];
    #pragma unroll
    for (int li = 0; li < 32; li++) {
        float v = (sm[li*257 + t] - s_mu[li]) * s_rs[li];
        g_xnh[((size_t)(b*LSEQ + l0 + li))*CDIM + t] = __float2bfloat16(fmaf(v, g, be));
    }
}

// ---------------- bf16 mma.sync GEMM, 3-stage cp.async, 1 sync/iter ----------------
// MODE 0: fp32 out -> Cf (ldc)
// MODE 1: col<512 -> u bf16 (g_uh); col>=512 -> silu -> g_gzh (both [row][d])
// MODE 2: dt = softplus(v + e0[col]); pack (dt,u2) -> g_du [row][d]
// MODE 3: BN=32 (WN=32): g_bc[row*16+s] = (D[s], D[s+16])
template<int BM, int BN, int WM, int WN, int MODE>
__global__ __launch_bounds__(256) void gemm_mma(
    const bf16* __restrict__ A, const bf16* __restrict__ Bt,
    float* __restrict__ Cf, const float* __restrict__ e0,
    int K, int ldc)
{
    constexpr int BK = 32, ST = 3;
    constexpr int LDA = BK + 8;
    constexpr int LDW = LDA / 2;
    extern __shared__ bf16 sm[];
    bf16* As = sm;
    bf16* Bs = sm + (size_t)ST*BM*LDA;
    const int tid = threadIdx.x, wid = tid >> 5, lane = tid & 31;
    const int g = lane >> 2, q = lane & 3;
    constexpr int NWN = BN / WN;
    const int wm = wid / NWN, wn = wid % NWN;
    const int m0 = blockIdx.y * BM, n0 = blockIdx.x * BN;
    constexpr int MF = WM / 16, NF = WN / 8;
    float acc[MF][NF][4] = {};

    auto load_stage = [&](int s, int kt) {
        const int k0 = kt * BK;
        #pragma unroll
        for (int i = 0; i < BM*4/256; i++) {
            int idx = tid + i*256;
            int r = idx >> 2, c = idx & 3;
            cp16(smem_u32(&As[(s*BM + r)*LDA + c*8]), &A[(size_t)(m0+r)*K + k0 + c*8]);
        }
        #pragma unroll
        for (int i = 0; i < (BN*4 + 255)/256; i++) {
            int idx = tid + i*256;
            if ((BN*4) % 256 == 0 || idx < BN*4) {
                int r = idx >> 2, c = idx & 3;
                cp16(smem_u32(&Bs[(s*BN + r)*LDA + c*8]), &Bt[(size_t)(n0+r)*K + k0 + c*8]);
            }
        }
        asm volatile("cp.async.commit_group;\n");
    };
    auto compute = [&](int s) {
        const uint32_t* A32 = (const uint32_t*)(As + (size_t)s*BM*LDA);
        const uint32_t* B32 = (const uint32_t*)(Bs + (size_t)s*BN*LDA);
        #pragma unroll
        for (int h = 0; h < 2; h++) {
            uint32_t af[MF][4], bfr[NF][2];
            #pragma unroll
            for (int i = 0; i < MF; i++) {
                int r = wm*WM + i*16 + g;
                af[i][0] = A32[(r  )*LDW + h*8 + q];
                af[i][1] = A32[(r+8)*LDW + h*8 + q];
                af[i][2] = A32[(r  )*LDW + h*8 + q + 4];
                af[i][3] = A32[(r+8)*LDW + h*8 + q + 4];
            }
            #pragma unroll
            for (int j = 0; j < NF; j++) {
                int c = wn*WN + j*8 + g;
                bfr[j][0] = B32[c*LDW + h*8 + q];
                bfr[j][1] = B32[c*LDW + h*8 + q + 4];
            }
            #pragma unroll
            for (int i = 0; i < MF; i++)
                #pragma unroll
                for (int j = 0; j < NF; j++)
                    mma16(acc[i][j], af[i], bfr[j]);
        }
    };

    const int nk = K / BK;
    load_stage(0, 0);
    load_stage(1, 1);
    #pragma unroll 1
    for (int kt = 0; kt < nk; kt++) {
        asm volatile("cp.async.wait_group 1;\n");
        __syncthreads();
        int nx = kt + 2;
        if (nx < nk) load_stage(nx % ST, nx);
        else asm volatile("cp.async.commit_group;\n");
        compute(kt % ST);
    }

    // ----- epilogue (row-major, coalesced; verified in R6) -----
    #pragma unroll
    for (int i = 0; i < MF; i++) {
        int row = m0 + wm*WM + i*16 + g;
        if (MODE == 3) {
            #pragma unroll
            for (int j = 0; j < 2; j++) {
                int s = j*8 + 2*q;
                float4 lo = make_float4(acc[i][j][0], acc[i][j+2][0],
                                        acc[i][j][1], acc[i][j+2][1]);
                float4 hi = make_float4(acc[i][j][2], acc[i][j+2][2],
                                        acc[i][j][3], acc[i][j+2][3]);
                *(float4*)&g_bc[(size_t)(row  )*DSTATE + s] = lo;
                *(float4*)&g_bc[(size_t)(row+8)*DSTATE + s] = hi;
            }
        } else {
            #pragma unroll
            for (int j = 0; j < NF; j++) {
                int col = n0 + wn*WN + j*8 + 2*q;
                float v0 = acc[i][j][0], v1 = acc[i][j][1];
                float v2 = acc[i][j][2], v3 = acc[i][j][3];
                if (MODE == 0) {
                    *(float2*)&Cf[(size_t)(row  )*ldc + col] = make_float2(v0, v1);
                    *(float2*)&Cf[(size_t)(row+8)*ldc + col] = make_float2(v2, v3);
                } else if (MODE == 1) {
                    if (col < DINNER) {
                        *(uint32_t*)&g_uh[(size_t)(row  )*DINNER + col] = pbf2(v0, v1);
                        *(uint32_t*)&g_uh[(size_t)(row+8)*DINNER + col] = pbf2(v2, v3);
                    } else {
                        int cz = col - DINNER;
                        *(uint32_t*)&g_gzh[(size_t)(row  )*DINNER + cz] =
                            pbf2(siluf(v0), siluf(v1));
                        *(uint32_t*)&g_gzh[(size_t)(row+8)*DINNER + cz] =
                            pbf2(siluf(v2), siluf(v3));
                    }
                } else { // MODE 2: (dt,u2) pack, dt in low 16, u2 in high 16
                    float b0 = e0[col], b1 = e0[col+1];
                    uint32_t ua = *(const uint32_t*)&g_u2h[(size_t)(row  )*DINNER + col];
                    uint32_t ub = *(const uint32_t*)&g_u2h[(size_t)(row+8)*DINNER + col];
                    uint32_t d0 = (uint32_t)__bfloat16_as_ushort(__float2bfloat16(softplusf(v0 + b0)));
                    uint32_t d1 = (uint32_t)__bfloat16_as_ushort(__float2bfloat16(softplusf(v1 + b1)));
                    uint32_t d2 = (uint32_t)__bfloat16_as_ushort(__float2bfloat16(softplusf(v2 + b0)));
                    uint32_t d3 = (uint32_t)__bfloat16_as_ushort(__float2bfloat16(softplusf(v3 + b1)));
                    uint2 wa = make_uint2(d0 | ((ua & 0xFFFFu) << 16), d1 | (ua & 0xFFFF0000u));
                    uint2 wb = make_uint2(d2 | ((ub & 0xFFFFu) << 16), d3 | (ub & 0xFFFF0000u));
                    *(uint2*)&g_du[(size_t)(row  )*DINNER + col] = wa;
                    *(uint2*)&g_du[(size_t)(row+8)*DINNER + col] = wb;
                }
            }
        }
    }
}

// ---------------- depthwise causal conv (D_CONV=4) + SiLU, bf162 ----------------
__global__ __launch_bounds__(256) void conv_silu_kernel(const float* __restrict__ cw,
                                                        const float* __restrict__ cb) {
    int gid = blockIdx.x*256 + threadIdx.x;
    int d2  = gid & 255;
    int row = gid >> 8;
    int l   = row & (LSEQ-1);
    int d   = d2 * 2;
    float a0 = cb[d], a1 = cb[d+1];
    const uint32_t* up = (const uint32_t*)g_uh;
    #pragma unroll
    for (int k = 0; k < 4; k++) {
        int ll = l - 3 + k;
        if (ll >= 0) {
            uint32_t w = up[(size_t)(row - 3 + k)*256 + d2];
            bf162 p = *(bf162*)&w;
            a0 = fmaf(__bfloat162float(p.x), cw[d*4 + k],     a0);
            a1 = fmaf(__bfloat162float(p.y), cw[(d+1)*4 + k], a1);
        }
    }
    ((uint32_t*)g_u2h)[gid] = pbf2(siluf(a0), siluf(a1));
}

// ---------------- selective scan v3: row-major inputs, smem-tiled, prefetch ----------
// block = 256 thr = 8 warps; batch b = blockIdx>>5, channels dblk..dblk+15.
// warp = 2 chains (ch = 2*widx + half), 16-lane group = states s=0..15.
// Chunk of 16 timesteps staged in smem; all gmem traffic coalesced row-major.
__global__ __launch_bounds__(256) void scan_kernel(const float* __restrict__ A_log,
                                                   const float* __restrict__ D_skip) {
    __shared__ uint32_t       s_du[16][16];
    __shared__ float2         s_bc[16][16];
    __shared__ unsigned short s_gz[16][16];
    __shared__ unsigned short s_yg[16][16];
    const int b    = blockIdx.x >> 5;
    const int dblk = (blockIdx.x & 31) * 16;
    const int tid  = threadIdx.x;
    const int widx = tid >> 5, lane = tid & 31;
    const int half = lane >> 4, s = lane & 15;
    const int ch   = 2*widx + half;         // 0..15
    const int d    = dblk + ch;
    const float Aval = -__expf(A_log[d*DSTATE + s]);
    const float Dd   = D_skip[d];
    const size_t rb  = (size_t)b * LSEQ;
    const int li = tid >> 4, dd = tid & 15; // tile fill/flush mapping
    const uint32_t*       duG = g_du;
    const unsigned short* gzG = (const unsigned short*)g_gzh;
    unsigned short*       ygG = (unsigned short*)g_ygh;

    uint32_t r_du; unsigned short r_gz; float2 r_bc;
    auto ldchunk = [&](int c0) {
        size_t rw = (rb + c0 + li);
        r_du = duG[rw*DINNER + dblk + dd];
        r_gz = gzG[rw*DINNER + dblk + dd];
        r_bc = g_bc[rw*DSTATE + dd];
    };
    float h = 0.f;
    ldchunk(0);
    #pragma unroll 1
    for (int c0 = 0; c0 < LSEQ; c0 += 16) {
        __syncthreads();                 // prev compute + flush complete
        s_du[li][dd] = r_du;
        s_gz[li][dd] = r_gz;
        s_bc[li][dd] = r_bc;
        __syncthreads();                 // tiles ready
        if (c0 + 16 < LSEQ) ldchunk(c0 + 16);   // prefetch next chunk
        #pragma unroll
        for (int j = 0; j < 16; j++) {
            uint32_t w = s_du[j][ch];
            bf162 p = *(bf162*)&w;
            float dt = __bfloat162float(p.x);
            float u2 = __bfloat162float(p.y);
            float2 bcv = s_bc[j][s];
            float dA = __expf(dt * Aval);
            h = fmaf(dA, h, dt * u2 * bcv.x);
            float pr = h * bcv.y;
            pr += __shfl_xor_sync(0xffffffffu, pr, 8);
            pr += __shfl_xor_sync(0xffffffffu, pr, 4);
            pr += __shfl_xor_sync(0xffffffffu, pr, 2);
            pr += __shfl_xor_sync(0xffffffffu, pr, 1);
            if (s == j) {
                float yv = pr + u2 * Dd;
                float gzf = __bfloat162float(__ushort_as_bfloat16(s_gz[j][ch]));
                s_yg[j][ch] = __bfloat16_as_ushort(__float2bfloat16(yv * gzf));
            }
        }
        __syncthreads();                 // s_yg complete
        ygG[(rb + c0 + li)*DINNER + dblk + dd] = s_yg[li][dd];
    }
}

// ---------------- o(B,L,C) -> out(B,C,H,W) + residual x ----------------
__global__ __launch_bounds__(256) void out_kernel(const float* __restrict__ x,
                                                  float* __restrict__ out) {
    __shared__ float sm[32][33];
    const int b  = blockIdx.z;
    const int c0 = blockIdx.y * 32;
    const int l0 = blockIdx.x * 32;
    const int t  = threadIdx.x;
    const int ci = t & 31, lq = t >> 5;
    #pragma unroll
    for (int p = 0; p < 4; p++) {
        int li = p*8 + lq;
        sm[li][ci] = g_o[((size_t)(b*LSEQ + l0 + li))*CDIM + c0 + ci];
    }
    __syncthreads();
    const int li2 = t & 31, cq = t >> 5;
    #pragma unroll
    for (int p = 0; p < 4; p++) {
        int ci2 = p*8 + cq;
        size_t idx = ((size_t)(b*CDIM + c0 + ci2))*LSEQ + l0 + li2;
        out[idx] = sm[li2][ci2] + x[idx];
    }
}

// ---------------- host launch ----------------
extern "C" void kernel_launch(void* const* d_in, const int* in_sizes, int n_in,
                              void* d_out, int out_size) {
    const float* x       = (const float*)d_in[0];
    const float* ln_g    = (const float*)d_in[1];
    const float* ln_b    = (const float*)d_in[2];
    const float* W_in    = (const float*)d_in[3];
    const float* conv_w  = (const float*)d_in[4];
    const float* conv_b  = (const float*)d_in[5];
    const float* W_xproj = (const float*)d_in[6];
    const float* W_dt    = (const float*)d_in[7];
    const float* b_dt    = (const float*)d_in[8];
    const float* A_log   = (const float*)d_in[9];
    const float* D_skip  = (const float*)d_in[10];
    const float* W_out   = (const float*)d_in[11];
    float* out = (float*)d_out;

    bf16 *p_xnh, *p_u2h, *p_ygh, *p_WinT, *p_wcombT, *p_WbcT, *p_WoutT;
    float *p_o;
    cudaGetSymbolAddress((void**)&p_xnh,    g_xnh);
    cudaGetSymbolAddress((void**)&p_u2h,    g_u2h);
    cudaGetSymbolAddress((void**)&p_ygh,    g_ygh);
    cudaGetSymbolAddress((void**)&p_o,      g_o);
    cudaGetSymbolAddress((void**)&p_WinT,   g_WinT);
    cudaGetSymbolAddress((void**)&p_wcombT, g_wcombT);
    cudaGetSymbolAddress((void**)&p_WbcT,   g_WbcT);
    cudaGetSymbolAddress((void**)&p_WoutT,  g_WoutT);

    const int SMB128 = 3*(128+128)*40*2;   // 61440
    const int SMB32  = 3*(128+32)*40*2;    // 38400
    cudaFuncSetAttribute(gemm_mma<128,128,64,32,0>, cudaFuncAttributeMaxDynamicSharedMemorySize, SMB128);
    cudaFuncSetAttribute(gemm_mma<128,128,64,32,1>, cudaFuncAttributeMaxDynamicSharedMemorySize, SMB128);
    cudaFuncSetAttribute(gemm_mma<128,128,64,32,2>, cudaFuncAttributeMaxDynamicSharedMemorySize, SMB128);
    cudaFuncSetAttribute(gemm_mma<128,32,16,32,3>,  cudaFuncAttributeMaxDynamicSharedMemorySize, SMB32);

    // launch index:                                   (ncu captures index 3)
    prepA_kernel<<<dim3(32, 8), 256>>>(W_in);                          // 0
    prepB_kernel<<<656, 256>>>(W_out, W_xproj, W_dt);                  // 1
    ln_kernel<<<BATCH*32, 256>>>(x, ln_g, ln_b);                       // 2
    gemm_mma<128,128,64,32,1><<<dim3(8, 64), 256, SMB128>>>(           // 3  G1
        p_xnh, p_WinT, nullptr, nullptr, CDIM, 0);
    conv_silu_kernel<<<NROWS, 256>>>(conv_w, conv_b);                  // 4
    gemm_mma<128,128,64,32,2><<<dim3(4, 64), 256, SMB128>>>(           // 5  G2
        p_u2h, p_wcombT, nullptr, b_dt, DINNER, 0);
    gemm_mma<128,32,16,32,3><<<dim3(1, 64), 256, SMB32>>>(             // 6  G3
        p_u2h, p_WbcT, nullptr, nullptr, DINNER, 0);
    scan_kernel<<<256, 256>>>(A_log, D_skip);                          // 7
    gemm_mma<128,128,64,32,0><<<dim3(2, 64), 256, SMB128>>>(           // 8  G4
        p_ygh, p_WoutT, p_o, nullptr, DINNER, CDIM);
    out_kernel<<<dim3(32, 8, 8), 256>>>(x, out);                       // 9
}